// round 12
// baseline (speedup 1.0000x reference)
#include <cuda_runtime.h>

#define FULL 0xffffffffu

static constexpr int B_ = 64;
static constexpr int S_ = 12;
static constexpr int N_ = 207;
static constexpr int F_ = 2;
static constexpr int NCIRC = B_ * N_;       // 13248
static constexpr int CPB = 8;               // circuits per 128-thread block
static constexpr float PI_F = 3.14159265358979323846f;

// Each warp-PAIR handles 4 circuits: even warp = re component, odd warp = im.
// Within a warp: 4 groups of 8 lanes, one circuit per group.
// Flat j (8 bits) = (g << 5) | r;  g = lane & 7, r = reg idx (5 bits).
// qubit -> j-bit: q0->7 q5->6 q7->5 (lane g bits 2,1,0)
//                 q1->4 q2->3 q3->2 q4->1 q6->0 (reg bits 4..0)

__device__ __forceinline__ float shx(float v, int m) { return __shfl_xor_sync(FULL, v, m); }

// ---- RY on a register bit P (single component) ----
template<int P>
__device__ __forceinline__ void ry_reg(float (&st)[32], float c, float s) {
    constexpr int m = 1 << P;
    #pragma unroll
    for (int r = 0; r < 32; ++r) if (!(r & m)) {
        const int r1 = r | m;
        float a0 = st[r], a1 = st[r1];
        st[r]  = fmaf(c, a0, -s * a1);
        st[r1] = fmaf(s, a0,  c * a1);
    }
}

// ---- RY on a lane bit LB ----
template<int LB>
__device__ __forceinline__ void ry_lane(float (&st)[32], float c, float s, int lane) {
    constexpr int L = 1 << LB;
    const float sg = ((lane >> LB) & 1) ? s : -s;
    #pragma unroll
    for (int r = 0; r < 32; ++r) {
        float p = shx(st[r], L);
        st[r] = fmaf(c, st[r], sg * p);
    }
}

// ---- fused conv pair, both qubits reg bits (PA first, PB second) ----
template<int PA, int PB>
__device__ __forceinline__ void conv_rr(float (&st)[32], const float4* __restrict__ U4) {
    const float4 a0 = U4[0], a1 = U4[1], a2 = U4[2], a3 = U4[3];
    constexpr int ma = 1 << PA, mb = 1 << PB;
    #pragma unroll
    for (int r0 = 0; r0 < 32; ++r0) if (!(r0 & (ma | mb))) {
        const int i1 = r0 | mb, i2 = r0 | ma, i3 = r0 | ma | mb;
        float v0 = st[r0], v1 = st[i1], v2 = st[i2], v3 = st[i3];
        st[r0] = fmaf(a0.x, v0, fmaf(a0.y, v1, fmaf(a0.z, v2, a0.w * v3)));
        st[i1] = fmaf(a1.x, v0, fmaf(a1.y, v1, fmaf(a1.z, v2, a1.w * v3)));
        st[i2] = fmaf(a2.x, v0, fmaf(a2.y, v1, fmaf(a2.z, v2, a2.w * v3)));
        st[i3] = fmaf(a3.x, v0, fmaf(a3.y, v1, fmaf(a3.z, v2, a3.w * v3)));
    }
}

// ---- fused conv pair, one qubit on lane bit LBIT, one on reg bit PB.
// Coefficients pre-arranged in shared: T2[2a] = {u00,u01,u02,u03}, T2[2a+1] = {u10..u13}.
template<int LBIT, int PB>
__device__ __forceinline__ void conv_mx(float (&st)[32], const float4* __restrict__ T2, int lane) {
    constexpr int Lm = 1 << LBIT, mb = 1 << PB;
    const int a = (lane >> LBIT) & 1;
    const float4 ua = T2[2 * a];
    const float4 ub = T2[2 * a + 1];
    #pragma unroll
    for (int r0 = 0; r0 < 32; ++r0) if (!(r0 & mb)) {
        const int r1 = r0 | mb;
        float p0 = shx(st[r0], Lm), p1 = shx(st[r1], Lm);
        float o0 = st[r0], o1 = st[r1];
        st[r0] = fmaf(ua.x, o0, fmaf(ua.y, o1, fmaf(ua.z, p0, ua.w * p1)));
        st[r1] = fmaf(ub.x, o0, fmaf(ub.y, o1, fmaf(ub.z, p0, ub.w * p1)));
    }
}

__global__ __launch_bounds__(128, 7)
void qcnn_kernel(const float* __restrict__ x, const float* __restrict__ adj,
                 const float* __restrict__ w_proj, const float* __restrict__ b_proj,
                 const float* __restrict__ qp,
                 const float* __restrict__ w1, const float* __restrict__ b1,
                 const float* __restrict__ w2, const float* __restrict__ b2,
                 const float* __restrict__ w3, const float* __restrict__ b3,
                 float* __restrict__ out) {
    __shared__ alignas(16) float UUs[14][16];      // full fused conv matrices (rr gates)
    __shared__ alignas(16) float UMX[8][2][8];     // mx gates: [gate][laneBit a][8 coefs]
    __shared__ float poolc[4], pools[4];
    __shared__ alignas(16) float w1s[512];         // w1 natural [64][8]
    __shared__ float4 w2p4[32 * 17];               // w2 rows padded to 68 floats
    __shared__ float4 h1buf4[CPB * 17];
    __shared__ float zbuf[CPB][8];                 // im-warp partial z
    __shared__ float b1s[64], b2s[32], w3s[32];
    __shared__ float b3s;

    const int tid = threadIdx.x;

    // ---- build fused conv matrices U = C2 * G2 * C1 * G1 ----
    if (tid < 14) {
        const int layer = tid / 7, pi = tid - 7 * layer;
        const int base = layer * 28 + pi * 4;
        float c0, s0, c1, s1, c2, s2, c3, s3;
        sincosf(0.5f * qp[base + 0], &s0, &c0);
        sincosf(0.5f * qp[base + 1], &s1, &c1);
        sincosf(0.5f * qp[base + 2], &s2, &c2);
        sincosf(0.5f * qp[base + 3], &s3, &c3);
        float R0[2][2] = {{c0, -s0}, {s0, c0}};
        float R1[2][2] = {{c1, -s1}, {s1, c1}};
        float R2m[2][2] = {{c2, -s2}, {s2, c2}};
        float R3[2][2] = {{c3, -s3}, {s3, c3}};
        float A[4][4], G2m[4][4], Bm[4][4], Cm[4][4];
        #pragma unroll
        for (int ap = 0; ap < 2; ++ap)
        #pragma unroll
        for (int bp = 0; bp < 2; ++bp)
        #pragma unroll
        for (int aq = 0; aq < 2; ++aq)
        #pragma unroll
        for (int bq = 0; bq < 2; ++bq) {
            A[2 * ap + bp][2 * aq + bq]   = R0[ap][aq] * R1[bp][bq];
            G2m[2 * ap + bp][2 * aq + bq] = R2m[ap][aq] * R3[bp][bq];
        }
        const int sig1[4] = {0, 1, 3, 2};
        const int sig2[4] = {0, 3, 2, 1};
        #pragma unroll
        for (int xr = 0; xr < 4; ++xr)
            #pragma unroll
            for (int m = 0; m < 4; ++m) Bm[xr][m] = A[sig1[xr]][m];
        #pragma unroll
        for (int xr = 0; xr < 4; ++xr)
            #pragma unroll
            for (int m = 0; m < 4; ++m) {
                float acc = 0.f;
                #pragma unroll
                for (int y = 0; y < 4; ++y) acc = fmaf(G2m[xr][y], Bm[y][m], acc);
                Cm[xr][m] = acc;
            }
        float Uf[16];
        #pragma unroll
        for (int xr = 0; xr < 4; ++xr)
            #pragma unroll
            for (int m = 0; m < 4; ++m) {
                Uf[xr * 4 + m] = Cm[sig2[xr]][m];
                UUs[tid][xr * 4 + m] = Cm[sig2[xr]][m];
            }
        // mx-gate coefficient tables. gates-in-layer 0,2,3,6 are mixed;
        // LQ1 (lane qubit first in the pair) for 0 and 6.
        int mxslot = -1; bool lq1 = false;
        if (pi == 0) { mxslot = 0; lq1 = true; }
        else if (pi == 2) { mxslot = 1; lq1 = false; }
        else if (pi == 3) { mxslot = 2; lq1 = false; }
        else if (pi == 6) { mxslot = 3; lq1 = true; }
        if (mxslot >= 0) {
            #pragma unroll
            for (int a = 0; a < 2; ++a) {
                int r0, r1, d0, d1;
                if (lq1) { r0 = 2 * a; r1 = 2 * a + 1; d0 = 2 * (a ^ 1); d1 = d0 + 1; }
                else     { r0 = a;     r1 = 2 + a;     d0 = a ^ 1;       d1 = 2 + (a ^ 1); }
                float* dst = &UMX[layer * 4 + mxslot][a][0];
                dst[0] = Uf[r0 * 4 + r0]; dst[1] = Uf[r0 * 4 + r1];
                dst[2] = Uf[r0 * 4 + d0]; dst[3] = Uf[r0 * 4 + d1];
                dst[4] = Uf[r1 * 4 + r0]; dst[5] = Uf[r1 * 4 + r1];
                dst[6] = Uf[r1 * 4 + d0]; dst[7] = Uf[r1 * 4 + d1];
            }
        }
    }
    if (tid >= 16 && tid < 20) {
        float s, c;
        sincosf(0.5f * qp[56 + 2 * (tid - 16)], &s, &c);
        poolc[tid - 16] = c; pools[tid - 16] = s;
    }
    for (int i = tid; i < 512; i += 128) w1s[i] = w1[i];
    for (int i = tid; i < 2048; i += 128) {
        int row = i >> 6, j = i & 63;
        ((float*)w2p4)[row * 68 + j] = w2[i];
    }
    if (tid < 64) b1s[tid] = b1[tid];
    if (tid >= 64 && tid < 96) b2s[tid - 64] = b2[tid - 64];
    if (tid >= 96 && tid < 128) w3s[tid - 96] = w3[tid - 96];
    if (tid == 20) b3s = b3[0];
    __syncthreads();

    const int wid = tid >> 5;
    const int lane = tid & 31;
    const int comp = wid & 1;                 // 0 = re warp, 1 = im warp
    const int pairid = wid >> 1;              // 0..1
    const int ci = lane >> 3;                 // circuit-in-warp
    const int g = lane & 7;
    const int cb = pairid * 4 + ci;           // circuit-in-block 0..7
    const int cir = blockIdx.x * CPB + cb;
    const int b = cir / N_;
    const int n = cir - b * N_;

    // ---- angle projection: lane computes angle q = g of its circuit ----
    float av;
    {
        av = b_proj[g];
        const float* wrow = w_proj + g * (S_ * F_);
        const float* xb = x + (size_t)b * (S_ * N_ * F_) + n * F_;
        #pragma unroll
        for (int s = 0; s < S_; ++s) {
            float2 xv = *(const float2*)(xb + s * (N_ * F_));
            av = fmaf(wrow[2 * s], xv.x, av);
            av = fmaf(wrow[2 * s + 1], xv.y, av);
        }
        av = fminf(fmaxf(av, -PI_F), PI_F);
    }
    float sv, cv;
    sincosf(0.5f * av, &sv, &cv);
    float ch[8], sh[8];
    #pragma unroll
    for (int q = 0; q < 8; ++q) {
        ch[q] = __shfl_sync(FULL, cv, (lane & 24) | q);
        sh[q] = __shfl_sync(FULL, sv, (lane & 24) | q);
    }

    // ---- initial product state (this warp's component only) ----
    const int bq0 = (g >> 2) & 1, bq5 = (g >> 1) & 1, bq7 = g & 1;
    float magL = (bq0 ? sh[0] : ch[0]) * (bq5 ? sh[5] : ch[5]) * (bq7 ? sh[7] : ch[7]);
    const float sL = bq0 ? sh[4] : -sh[4];   // RZ(a4) on q0
    float ml[4];
    #pragma unroll
    for (int l = 0; l < 4; ++l)
        ml[l] = ((l >> 1) ? sh[4] : ch[4]) * ((l & 1) ? sh[6] : ch[6]);

    float st[32];
    #pragma unroll
    for (int t = 0; t < 8; ++t) {
        float s1 = (t & 4) ? sh[5] : -sh[5];
        float er = fmaf(ch[4], ch[5], -sL * s1);
        float ei = fmaf(ch[4], s1, sL * ch[5]);
        float s2 = (t & 2) ? sh[6] : -sh[6];
        float er2 = fmaf(er, ch[6], -ei * s2);
        float ei2 = fmaf(er, s2, ei * ch[6]);
        float s3 = (t & 1) ? sh[7] : -sh[7];
        float er3 = fmaf(er2, ch[7], -ei2 * s3);
        float ei3 = fmaf(er2, s3, ei2 * ch[7]);
        float m = magL * ((t & 4) ? sh[1] : ch[1]) * ((t & 2) ? sh[2] : ch[2])
                       * ((t & 1) ? sh[3] : ch[3]);
        const float tvt = m * (comp ? ei3 : er3);
        st[4 * t + 0] = tvt * ml[0];
        st[4 * t + 1] = tvt * ml[1];
        st[4 * t + 2] = tvt * ml[2];
        st[4 * t + 3] = tvt * ml[3];
    }

    // ---- graph CNOTs: composed conditional XOR permutation ----
    const int c = n & 7;
    const int pcq = (0x50612347u >> (4 * c)) & 0xF;    // posOf[c]
    int cond = (adj[c * N_ + g] > 0.f) && (g != c);
    const unsigned bal = __ballot_sync(FULL, cond);
    const unsigned mask8 = (bal >> (ci * 8)) & 0xFFu;
    constexpr int posOf[8] = {7, 4, 3, 2, 1, 6, 0, 5};
    int M = 0;
    #pragma unroll
    for (int t = 0; t < 8; ++t) M |= (int)((mask8 >> t) & 1u) << posOf[t];
    const int glm = (M >> 5) & 7;
    const int MR = M & 31;
    const int jbase = g << 5;
    // lane pass
    #pragma unroll
    for (int r = 0; r < 32; ++r) {
        const int bc = ((jbase | r) >> pcq) & 1;
        const int src = (lane & 24) | (bc ? (g ^ glm) : g);
        st[r] = __shfl_sync(FULL, st[r], src);
    }
    // register-bit passes (predicated swaps, pure ALU)
    #pragma unroll
    for (int t = 0; t < 5; ++t) {
        const int mt = 1 << t;
        const bool sw = (MR >> t) & 1;
        #pragma unroll
        for (int r0 = 0; r0 < 32; ++r0) if (!(r0 & mt)) {
            const int r1 = r0 | mt;
            const bool cnd = sw && (((jbase | r0) >> pcq) & 1);
            float t0 = st[r0], t1 = st[r1];
            st[r0] = cnd ? t1 : t0;  st[r1] = cnd ? t0 : t1;
        }
    }

    // ---- 2 conv layers ----
    #pragma unroll
    for (int l = 0; l < 2; ++l) {
        const float4* Ub = (const float4*)UUs[l * 7];
        conv_mx<2, 4>(st, (const float4*)UMX[l * 4 + 0], lane);   // (q0,q1)
        conv_rr<3, 2>(st, Ub + 1 * 4);                            // (q2,q3)
        conv_mx<1, 1>(st, (const float4*)UMX[l * 4 + 1], lane);   // (q4,q5)
        conv_mx<0, 0>(st, (const float4*)UMX[l * 4 + 2], lane);   // (q6,q7)
        conv_rr<4, 3>(st, Ub + 4 * 4);                            // (q1,q2)
        conv_rr<2, 1>(st, Ub + 5 * 4);                            // (q3,q4)
        conv_mx<1, 0>(st, (const float4*)UMX[l * 4 + 3], lane);   // (q5,q6)
    }

    // ---- pooling RY on q0, q2, q4, q6 ----
    ry_lane<2>(st, poolc[0], pools[0], lane);  // q0 (lane bit 2)
    ry_reg<3>(st, poolc[1], pools[1]);         // q2
    ry_reg<1>(st, poolc[2], pools[2]);         // q4
    ry_reg<0>(st, poolc[3], pools[3]);         // q6

    // ---- partial <Z_w> from this component ----
    float tot = 0.f, z1 = 0.f, z2 = 0.f, z3 = 0.f, z4 = 0.f, z6 = 0.f;
    #pragma unroll
    for (int r = 0; r < 32; ++r) {
        float p = st[r] * st[r];
        tot += p;
        z1 += ((r >> 4) & 1) ? -p : p;
        z2 += ((r >> 3) & 1) ? -p : p;
        z3 += ((r >> 2) & 1) ? -p : p;
        z4 += ((r >> 1) & 1) ? -p : p;
        z6 += (r & 1) ? -p : p;
    }
    float z[8];
    z[0] = bq0 ? -tot : tot;
    z[5] = bq5 ? -tot : tot;
    z[7] = bq7 ? -tot : tot;
    z[1] = z1; z[2] = z2; z[3] = z3; z[4] = z4; z[6] = z6;
    #pragma unroll
    for (int off = 1; off < 8; off <<= 1) {
        #pragma unroll
        for (int w = 0; w < 8; ++w) z[w] += shx(z[w], off);
    }

    // im warp publishes its partial z; re warp combines and runs the MLP
    if (comp) zbuf[cb][g] = z[g];
    __syncthreads();

    if (!comp) {
        #pragma unroll
        for (int w = 0; w < 8; ++w) z[w] += zbuf[cb][w];

        // ---- MLP head: 8 -> 64 -> 32 -> 1 ----
        float h1v[8];
        const float* w1row = w1s + g * 64;
        #pragma unroll
        for (int i = 0; i < 8; ++i) {
            float4 wa = *(const float4*)(w1row + i * 8);
            float4 wb = *(const float4*)(w1row + i * 8 + 4);
            float acc = b1s[8 * g + i];
            acc = fmaf(wa.x, z[0], acc); acc = fmaf(wa.y, z[1], acc);
            acc = fmaf(wa.z, z[2], acc); acc = fmaf(wa.w, z[3], acc);
            acc = fmaf(wb.x, z[4], acc); acc = fmaf(wb.y, z[5], acc);
            acc = fmaf(wb.z, z[6], acc); acc = fmaf(wb.w, z[7], acc);
            h1v[i] = fmaxf(acc, 0.f);
        }
        {
            float4* dst = (float4*)((float*)h1buf4 + cb * 68 + 8 * g);
            dst[0] = make_float4(h1v[0], h1v[1], h1v[2], h1v[3]);
            dst[1] = make_float4(h1v[4], h1v[5], h1v[6], h1v[7]);
        }
        __syncwarp();

        // h2: this lane computes rows g, g+8, g+16, g+24
        float acc2[4];
        #pragma unroll
        for (int i = 0; i < 4; ++i) acc2[i] = b2s[g + 8 * i];
        const float4* h1p = h1buf4 + cb * 17;
        #pragma unroll
        for (int j4 = 0; j4 < 16; ++j4) {
            float4 h = h1p[j4];
            #pragma unroll
            for (int i = 0; i < 4; ++i) {
                float4 w = w2p4[(g + 8 * i) * 17 + j4];
                acc2[i] = fmaf(w.x, h.x, fmaf(w.y, h.y, fmaf(w.z, h.z, fmaf(w.w, h.w, acc2[i]))));
            }
        }
        float o = 0.f;
        #pragma unroll
        for (int i = 0; i < 4; ++i)
            o = fmaf(w3s[g + 8 * i], fmaxf(acc2[i], 0.f), o);
        o += shx(o, 1); o += shx(o, 2); o += shx(o, 4);
        if (g == 0) out[cir] = o + b3s;
    }
}

extern "C" void kernel_launch(void* const* d_in, const int* in_sizes, int n_in,
                              void* d_out, int out_size) {
    const float* x      = (const float*)d_in[0];
    const float* adj    = (const float*)d_in[1];
    const float* w_proj = (const float*)d_in[2];
    const float* b_proj = (const float*)d_in[3];
    const float* qp     = (const float*)d_in[4];
    const float* w1     = (const float*)d_in[5];
    const float* b1     = (const float*)d_in[6];
    const float* w2     = (const float*)d_in[7];
    const float* b2     = (const float*)d_in[8];
    const float* w3     = (const float*)d_in[9];
    const float* b3     = (const float*)d_in[10];
    float* out = (float*)d_out;

    const int blocks = NCIRC / CPB;   // 1656
    qcnn_kernel<<<blocks, 128>>>(x, adj, w_proj, b_proj, qp,
                                 w1, b1, w2, b2, w3, b3, out);
}

// round 13
// speedup vs baseline: 1.2030x; 1.2030x over previous
#include <cuda_runtime.h>

#define FULL 0xffffffffu

static constexpr int B_ = 64;
static constexpr int S_ = 12;
static constexpr int N_ = 207;
static constexpr int F_ = 2;
static constexpr int NCIRC = B_ * N_;       // 13248
static constexpr int CPB = 16;              // circuits per 256-thread block
static constexpr float PI_F = 3.14159265358979323846f;

// Each warp-PAIR handles 4 circuits: even warp = re component, odd warp = im.
// Within a warp: 4 groups of 8 lanes, one circuit per group.
// Flat j (8 bits) = (g << 5) | r;  g = lane & 7, r = reg idx (5 bits).
// qubit -> j-bit: q0->7 q5->6 q7->5 (lane g bits 2,1,0)
//                 q1->4 q2->3 q3->2 q4->1 q6->0 (reg bits 4..0)
// r = (t << 2) | l;  t = (q1,q2,q3) bits, l = (q4,q6) bits.

__device__ __forceinline__ float shx(float v, int m) { return __shfl_xor_sync(FULL, v, m); }

// ---- fused conv pair, both qubits reg bits (PA first, PB second) ----
template<int PA, int PB>
__device__ __forceinline__ void conv_rr(float (&st)[32], const float4* __restrict__ U4) {
    const float4 a0 = U4[0], a1 = U4[1], a2 = U4[2], a3 = U4[3];
    constexpr int ma = 1 << PA, mb = 1 << PB;
    #pragma unroll
    for (int r0 = 0; r0 < 32; ++r0) if (!(r0 & (ma | mb))) {
        const int i1 = r0 | mb, i2 = r0 | ma, i3 = r0 | ma | mb;
        float v0 = st[r0], v1 = st[i1], v2 = st[i2], v3 = st[i3];
        st[r0] = fmaf(a0.x, v0, fmaf(a0.y, v1, fmaf(a0.z, v2, a0.w * v3)));
        st[i1] = fmaf(a1.x, v0, fmaf(a1.y, v1, fmaf(a1.z, v2, a1.w * v3)));
        st[i2] = fmaf(a2.x, v0, fmaf(a2.y, v1, fmaf(a2.z, v2, a2.w * v3)));
        st[i3] = fmaf(a3.x, v0, fmaf(a3.y, v1, fmaf(a3.z, v2, a3.w * v3)));
    }
}

// ---- fused conv pair, one qubit on lane bit LBIT, one on reg bit PB.
// LQ1 = true: lane qubit is the FIRST of the pair (basis 2*first+second).
template<int LBIT, int PB, bool LQ1>
__device__ __forceinline__ void conv_mx(float (&st)[32], const float4* __restrict__ U4, int lane) {
    constexpr int Lm = 1 << LBIT, mb = 1 << PB;
    const int a = (lane >> LBIT) & 1;
    float4 u0, u1;
    if (LQ1) { u0 = U4[2 * a]; u1 = U4[2 * a + 1]; }
    else     { u0 = U4[a];     u1 = U4[2 + a]; }
    float u00, u01, u02, u03, u10, u11, u12, u13;
    if (LQ1) {
        u00 = a ? u0.z : u0.x;  u01 = a ? u0.w : u0.y;
        u02 = a ? u0.x : u0.z;  u03 = a ? u0.y : u0.w;
        u10 = a ? u1.z : u1.x;  u11 = a ? u1.w : u1.y;
        u12 = a ? u1.x : u1.z;  u13 = a ? u1.y : u1.w;
    } else {
        u00 = a ? u0.y : u0.x;  u01 = a ? u0.w : u0.z;
        u02 = a ? u0.x : u0.y;  u03 = a ? u0.z : u0.w;
        u10 = a ? u1.y : u1.x;  u11 = a ? u1.w : u1.z;
        u12 = a ? u1.x : u1.y;  u13 = a ? u1.z : u1.w;
    }
    #pragma unroll
    for (int r0 = 0; r0 < 32; ++r0) if (!(r0 & mb)) {
        const int r1 = r0 | mb;
        float p0 = shx(st[r0], Lm), p1 = shx(st[r1], Lm);
        float o0 = st[r0], o1 = st[r1];
        st[r0] = fmaf(u00, o0, fmaf(u01, o1, fmaf(u02, p0, u03 * p1)));
        st[r1] = fmaf(u10, o0, fmaf(u11, o1, fmaf(u12, p0, u13 * p1)));
    }
}

__global__ __launch_bounds__(256, 3)
void qcnn_kernel(const float* __restrict__ x, const float* __restrict__ adj,
                 const float* __restrict__ w_proj, const float* __restrict__ b_proj,
                 const float* __restrict__ qp,
                 const float* __restrict__ w1, const float* __restrict__ b1,
                 const float* __restrict__ w2, const float* __restrict__ b2,
                 const float* __restrict__ w3, const float* __restrict__ b3,
                 float* __restrict__ out) {
    __shared__ alignas(16) float UUs[14][16];
    __shared__ float poolc[4], pools[4];           // FULL-angle cos/sin of pool RYs
    __shared__ alignas(16) float w1s[512];         // w1 natural [64][8]
    __shared__ float4 w2p4[32 * 17];               // w2 rows padded to 68 floats
    __shared__ float4 h1buf4[CPB * 17];
    __shared__ float zbuf[CPB][8];                 // im-warp partial z
    __shared__ float b1s[64], b2s[32], w3s[32];
    __shared__ float b3s;

    const int tid = threadIdx.x;

    // ---- build fused conv matrices U = C2 * G2 * C1 * G1 ----
    if (tid < 14) {
        const int layer = tid / 7, pi = tid - 7 * layer;
        const int base = layer * 28 + pi * 4;
        float c0, s0, c1, s1, c2, s2, c3, s3;
        sincosf(0.5f * qp[base + 0], &s0, &c0);
        sincosf(0.5f * qp[base + 1], &s1, &c1);
        sincosf(0.5f * qp[base + 2], &s2, &c2);
        sincosf(0.5f * qp[base + 3], &s3, &c3);
        float R0[2][2] = {{c0, -s0}, {s0, c0}};
        float R1[2][2] = {{c1, -s1}, {s1, c1}};
        float R2m[2][2] = {{c2, -s2}, {s2, c2}};
        float R3[2][2] = {{c3, -s3}, {s3, c3}};
        float A[4][4], G2m[4][4], Bm[4][4], Cm[4][4];
        #pragma unroll
        for (int ap = 0; ap < 2; ++ap)
        #pragma unroll
        for (int bp = 0; bp < 2; ++bp)
        #pragma unroll
        for (int aq = 0; aq < 2; ++aq)
        #pragma unroll
        for (int bq = 0; bq < 2; ++bq) {
            A[2 * ap + bp][2 * aq + bq]   = R0[ap][aq] * R1[bp][bq];
            G2m[2 * ap + bp][2 * aq + bq] = R2m[ap][aq] * R3[bp][bq];
        }
        const int sig1[4] = {0, 1, 3, 2};
        const int sig2[4] = {0, 3, 2, 1};
        #pragma unroll
        for (int xr = 0; xr < 4; ++xr)
            #pragma unroll
            for (int m = 0; m < 4; ++m) Bm[xr][m] = A[sig1[xr]][m];
        #pragma unroll
        for (int xr = 0; xr < 4; ++xr)
            #pragma unroll
            for (int m = 0; m < 4; ++m) {
                float acc = 0.f;
                #pragma unroll
                for (int y = 0; y < 4; ++y) acc = fmaf(G2m[xr][y], Bm[y][m], acc);
                Cm[xr][m] = acc;
            }
        #pragma unroll
        for (int xr = 0; xr < 4; ++xr)
            #pragma unroll
            for (int m = 0; m < 4; ++m) UUs[tid][xr * 4 + m] = Cm[sig2[xr]][m];
    }
    if (tid >= 16 && tid < 20) {
        float s, c;
        sincosf(qp[56 + 2 * (tid - 16)], &s, &c);   // FULL angle (fused pooling)
        poolc[tid - 16] = c; pools[tid - 16] = s;
    }
    for (int i = tid; i < 512; i += 256) w1s[i] = w1[i];
    for (int i = tid; i < 2048; i += 256) {
        int row = i >> 6, j = i & 63;
        ((float*)w2p4)[row * 68 + j] = w2[i];
    }
    if (tid < 64) b1s[tid] = b1[tid];
    if (tid >= 64 && tid < 96) b2s[tid - 64] = b2[tid - 64];
    if (tid >= 96 && tid < 128) w3s[tid - 96] = w3[tid - 96];
    if (tid == 20) b3s = b3[0];
    __syncthreads();

    const int wid = tid >> 5;
    const int lane = tid & 31;
    const int comp = wid & 1;                 // 0 = re warp, 1 = im warp
    const int pairid = wid >> 1;              // 0..3
    const int ci = lane >> 3;                 // circuit-in-warp
    const int g = lane & 7;
    const int cb = pairid * 4 + ci;           // circuit-in-block 0..15
    const int cir = blockIdx.x * CPB + cb;
    const int b = cir / N_;
    const int n = cir - b * N_;

    // ---- angle projection: lane computes angle q = g of its circuit ----
    float av;
    {
        av = b_proj[g];
        const float* wrow = w_proj + g * (S_ * F_);
        const float* xb = x + (size_t)b * (S_ * N_ * F_) + n * F_;
        #pragma unroll
        for (int s = 0; s < S_; ++s) {
            float2 xv = *(const float2*)(xb + s * (N_ * F_));
            av = fmaf(wrow[2 * s], xv.x, av);
            av = fmaf(wrow[2 * s + 1], xv.y, av);
        }
        av = fminf(fmaxf(av, -PI_F), PI_F);
    }
    float sv, cv;
    sincosf(0.5f * av, &sv, &cv);
    float ch[8], sh[8];
    #pragma unroll
    for (int q = 0; q < 8; ++q) {
        ch[q] = __shfl_sync(FULL, cv, (lane & 24) | q);
        sh[q] = __shfl_sync(FULL, sv, (lane & 24) | q);
    }

    // ---- graph CNOT mask (needed before construction) ----
    const int c = n & 7;
    const int pcq = (0x50612347u >> (4 * c)) & 0xF;    // posOf[c]
    int cond = (adj[c * N_ + g] > 0.f) && (g != c);
    const unsigned bal = __ballot_sync(FULL, cond);
    const unsigned mask8 = (bal >> (ci * 8)) & 0xFFu;
    constexpr int posOf[8] = {7, 4, 3, 2, 1, 6, 0, 5};
    int M = 0;
    #pragma unroll
    for (int t = 0; t < 8; ++t) M |= (int)((mask8 >> t) & 1u) << posOf[t];
    const int glm = (M >> 5) & 7;
    const int MR = M & 31;
    // bcmask bit r = control bit of flat index (g<<5)|r
    unsigned bcmask = (pcq == 0) ? 0xAAAAAAAAu : (pcq == 1) ? 0xCCCCCCCCu :
                      (pcq == 2) ? 0xF0F0F0F0u : (pcq == 3) ? 0xFF00FF00u : 0xFFFF0000u;
    if (pcq >= 5) bcmask = ((g >> (pcq - 5)) & 1) ? 0xFFFFFFFFu : 0u;

    // ---- build product state DIRECTLY PERMUTED by the graph CNOTs ----
    // st[r] = amp(j ^ (bc(j) ? M : 0)), j = (g<<5)|r, this warp's component.
    const int bq0 = (g >> 2) & 1, bq5 = (g >> 1) & 1, bq7 = g & 1;
    const int gp = g ^ glm;
    const int pp0 = (gp >> 2) & 1, pp5 = (gp >> 1) & 1, pp7 = gp & 1;

    const float magL0 = (bq0 ? sh[0] : ch[0]) * (bq5 ? sh[5] : ch[5]) * (bq7 ? sh[7] : ch[7]);
    const float magL1 = (pp0 ? sh[0] : ch[0]) * (pp5 ? sh[5] : ch[5]) * (pp7 ? sh[7] : ch[7]);
    const float ssA = bq0 ? sh[4] : -sh[4];    // RZ(a4) sign for own lane
    const float ssB = pp0 ? sh[4] : -sh[4];    // for partner lane
    const float ssx0 = comp ? ssA : -ssA;
    const float ssx1 = comp ? ssB : -ssB;

    // u23 = RZ phases of q2 (a6), q3 (a7) as complex, indexed by (t1,t0)
    float u23r[4], u23i[4];
    #pragma unroll
    for (int k = 0; k < 4; ++k) {
        const float s6 = (k & 2) ? sh[6] : -sh[6];
        const float s7 = (k & 1) ? sh[7] : -sh[7];
        u23r[k] = fmaf(ch[6], ch[7], -s6 * s7);
        u23i[k] = fmaf(ch[6], s7, s6 * ch[7]);
    }
    // B0[t]: own-lane t-factor; B1[t]: partner-lane variant
    float B0[8], B1[8];
    #pragma unroll
    for (int t = 0; t < 8; ++t) {
        const float s5 = (t & 4) ? sh[5] : -sh[5];                 // RZ(a5) on q1
        const float ur = fmaf(ch[5], u23r[t & 3], -s5 * u23i[t & 3]);
        const float ui = fmaf(ch[5], u23i[t & 3], s5 * u23r[t & 3]);
        const float P = comp ? ui : ur;
        const float Q = comp ? ur : ui;
        const float mg = ((t & 4) ? sh[1] : ch[1]) * ((t & 2) ? sh[2] : ch[2])
                       * ((t & 1) ? sh[3] : ch[3]);
        B0[t] = magL0 * mg * fmaf(ch[4], P, ssx0 * Q);
        B1[t] = magL1 * mg * fmaf(ch[4], P, ssx1 * Q);
    }
    // XOR-permute B1 by Mt and the l-factors by Mlr (compile-time index nets)
    const int Mt = (MR >> 2) & 7, Mlr = MR & 3;
    float Bp[8];
    {
        float ta[8], tb[8];
        #pragma unroll
        for (int t = 0; t < 8; ++t) ta[t] = (Mt & 1) ? B1[t ^ 1] : B1[t];
        #pragma unroll
        for (int t = 0; t < 8; ++t) tb[t] = (Mt & 2) ? ta[t ^ 2] : ta[t];
        #pragma unroll
        for (int t = 0; t < 8; ++t) Bp[t] = (Mt & 4) ? tb[t ^ 4] : tb[t];
    }
    float mA[4], mp[4];
    mA[0] = ch[4] * ch[6]; mA[1] = ch[4] * sh[6];
    mA[2] = sh[4] * ch[6]; mA[3] = sh[4] * sh[6];
    {
        float tm[4];
        #pragma unroll
        for (int l = 0; l < 4; ++l) tm[l] = (Mlr & 1) ? mA[l ^ 1] : mA[l];
        #pragma unroll
        for (int l = 0; l < 4; ++l) mp[l] = (Mlr & 2) ? tm[l ^ 2] : tm[l];
    }
    float st[32];
    #pragma unroll
    for (int t = 0; t < 8; ++t)
        #pragma unroll
        for (int l = 0; l < 4; ++l) {
            const int r = 4 * t + l;
            const bool bc = (bcmask >> r) & 1u;
            st[r] = (bc ? Bp[t] : B0[t]) * (bc ? mp[l] : mA[l]);
        }

    // ---- 2 conv layers ----
    #pragma unroll
    for (int l = 0; l < 2; ++l) {
        const float4* Ub = (const float4*)UUs[l * 7];
        conv_mx<2, 4, true>(st, Ub + 0 * 4, lane);    // (q0,q1)
        conv_rr<3, 2>(st, Ub + 1 * 4);                // (q2,q3)
        conv_mx<1, 1, false>(st, Ub + 2 * 4, lane);   // (q4,q5)
        conv_mx<0, 0, false>(st, Ub + 3 * 4, lane);   // (q6,q7)
        conv_rr<4, 3>(st, Ub + 4 * 4);                // (q1,q2)
        conv_rr<2, 1>(st, Ub + 5 * 4);                // (q3,q4)
        conv_mx<1, 0, true>(st, Ub + 6 * 4, lane);    // (q5,q6)
    }

    // ---- measurement with POOLING FUSED IN ----
    // z_q' = cosT*z_q_raw - sinT*2*sum(a0*a1) for pooled q in {0,2,4,6}
    float tot = 0.f, z1 = 0.f, z2 = 0.f, z3 = 0.f, z4 = 0.f, z6 = 0.f;
    float x2 = 0.f, x4 = 0.f, x6 = 0.f, c0x = 0.f;
    #pragma unroll
    for (int r = 0; r < 32; ++r) {
        float p = st[r] * st[r];
        tot += p;
        z1 += ((r >> 4) & 1) ? -p : p;
        z2 += ((r >> 3) & 1) ? -p : p;
        z3 += ((r >> 2) & 1) ? -p : p;
        z4 += ((r >> 1) & 1) ? -p : p;
        z6 += (r & 1) ? -p : p;
    }
    #pragma unroll
    for (int r = 0; r < 32; ++r) {
        if (!(r & 8)) x2 = fmaf(st[r], st[r | 8], x2);   // q2 pairs
        if (!(r & 2)) x4 = fmaf(st[r], st[r | 2], x4);   // q4 pairs
        if (!(r & 1)) x6 = fmaf(st[r], st[r | 1], x6);   // q6 pairs
    }
    #pragma unroll
    for (int r = 0; r < 32; ++r)
        c0x = fmaf(st[r], shx(st[r], 4), c0x);           // q0 cross (lane bit 2)

    float z[8];
    z[0] = fmaf(poolc[0], (bq0 ? -tot : tot), -pools[0] * c0x);
    z[2] = fmaf(poolc[1], z2, -2.f * pools[1] * x2);
    z[4] = fmaf(poolc[2], z4, -2.f * pools[2] * x4);
    z[6] = fmaf(poolc[3], z6, -2.f * pools[3] * x6);
    z[1] = z1; z[3] = z3;
    z[5] = bq5 ? -tot : tot;
    z[7] = bq7 ? -tot : tot;
    #pragma unroll
    for (int off = 1; off < 8; off <<= 1) {
        #pragma unroll
        for (int w = 0; w < 8; ++w) z[w] += shx(z[w], off);
    }

    // im warp publishes its partial z; re warp combines and runs the MLP
    if (comp) zbuf[cb][g] = z[g];
    __syncthreads();

    if (!comp) {
        #pragma unroll
        for (int w = 0; w < 8; ++w) z[w] += zbuf[cb][w];

        // ---- MLP head: 8 -> 64 -> 32 -> 1 ----
        float h1v[8];
        const float* w1row = w1s + g * 64;
        #pragma unroll
        for (int i = 0; i < 8; ++i) {
            float4 wa = *(const float4*)(w1row + i * 8);
            float4 wb = *(const float4*)(w1row + i * 8 + 4);
            float acc = b1s[8 * g + i];
            acc = fmaf(wa.x, z[0], acc); acc = fmaf(wa.y, z[1], acc);
            acc = fmaf(wa.z, z[2], acc); acc = fmaf(wa.w, z[3], acc);
            acc = fmaf(wb.x, z[4], acc); acc = fmaf(wb.y, z[5], acc);
            acc = fmaf(wb.z, z[6], acc); acc = fmaf(wb.w, z[7], acc);
            h1v[i] = fmaxf(acc, 0.f);
        }
        {
            float4* dst = (float4*)((float*)h1buf4 + cb * 68 + 8 * g);
            dst[0] = make_float4(h1v[0], h1v[1], h1v[2], h1v[3]);
            dst[1] = make_float4(h1v[4], h1v[5], h1v[6], h1v[7]);
        }
        __syncwarp();

        // h2: this lane computes rows g, g+8, g+16, g+24
        float acc2[4];
        #pragma unroll
        for (int i = 0; i < 4; ++i) acc2[i] = b2s[g + 8 * i];
        const float4* h1p = h1buf4 + cb * 17;
        #pragma unroll
        for (int j4 = 0; j4 < 16; ++j4) {
            float4 h = h1p[j4];
            #pragma unroll
            for (int i = 0; i < 4; ++i) {
                float4 w = w2p4[(g + 8 * i) * 17 + j4];
                acc2[i] = fmaf(w.x, h.x, fmaf(w.y, h.y, fmaf(w.z, h.z, fmaf(w.w, h.w, acc2[i]))));
            }
        }
        float o = 0.f;
        #pragma unroll
        for (int i = 0; i < 4; ++i)
            o = fmaf(w3s[g + 8 * i], fmaxf(acc2[i], 0.f), o);
        o += shx(o, 1); o += shx(o, 2); o += shx(o, 4);
        if (g == 0) out[cir] = o + b3s;
    }
}

extern "C" void kernel_launch(void* const* d_in, const int* in_sizes, int n_in,
                              void* d_out, int out_size) {
    const float* x      = (const float*)d_in[0];
    const float* adj    = (const float*)d_in[1];
    const float* w_proj = (const float*)d_in[2];
    const float* b_proj = (const float*)d_in[3];
    const float* qp     = (const float*)d_in[4];
    const float* w1     = (const float*)d_in[5];
    const float* b1     = (const float*)d_in[6];
    const float* w2     = (const float*)d_in[7];
    const float* b2     = (const float*)d_in[8];
    const float* w3     = (const float*)d_in[9];
    const float* b3     = (const float*)d_in[10];
    float* out = (float*)d_out;

    const int blocks = NCIRC / CPB;   // 828
    qcnn_kernel<<<blocks, 256>>>(x, adj, w_proj, b_proj, qp,
                                 w1, b1, w2, b2, w3, b3, out);
}

// round 14
// speedup vs baseline: 1.2359x; 1.0274x over previous
#include <cuda_runtime.h>

#define FULL 0xffffffffu

static constexpr int B_ = 64;
static constexpr int S_ = 12;
static constexpr int N_ = 207;
static constexpr int F_ = 2;
static constexpr int NCIRC = B_ * N_;       // 13248
static constexpr int CPB = 16;              // circuits per 256-thread block
static constexpr float PI_F = 3.14159265358979323846f;

// Each warp-PAIR handles 4 circuits: even warp = re component, odd warp = im.
// Within a warp: 4 groups of 8 lanes, one circuit per group.
// Flat j (8 bits) = (g << 5) | r;  g = lane & 7, r = reg idx (5 bits).
// qubit -> j-bit: q0->7 q5->6 q7->5 (lane g bits 2,1,0)
//                 q1->4 q2->3 q3->2 q4->1 q6->0 (reg bits 4..0)

__device__ __forceinline__ float shx(float v, int m) { return __shfl_xor_sync(FULL, v, m); }

// ---- fused conv pair, both qubits reg bits (PA first, PB second) ----
template<int PA, int PB>
__device__ __forceinline__ void conv_rr(float (&st)[32], const float4* __restrict__ U4) {
    const float4 a0 = U4[0], a1 = U4[1], a2 = U4[2], a3 = U4[3];
    constexpr int ma = 1 << PA, mb = 1 << PB;
    #pragma unroll
    for (int r0 = 0; r0 < 32; ++r0) if (!(r0 & (ma | mb))) {
        const int i1 = r0 | mb, i2 = r0 | ma, i3 = r0 | ma | mb;
        float v0 = st[r0], v1 = st[i1], v2 = st[i2], v3 = st[i3];
        st[r0] = fmaf(a0.x, v0, fmaf(a0.y, v1, fmaf(a0.z, v2, a0.w * v3)));
        st[i1] = fmaf(a1.x, v0, fmaf(a1.y, v1, fmaf(a1.z, v2, a1.w * v3)));
        st[i2] = fmaf(a2.x, v0, fmaf(a2.y, v1, fmaf(a2.z, v2, a2.w * v3)));
        st[i3] = fmaf(a3.x, v0, fmaf(a3.y, v1, fmaf(a3.z, v2, a3.w * v3)));
    }
}

// ---- fused conv pair, one qubit on lane bit LBIT, one on reg bit PB.
// Coefficients pre-arranged in shared: T2[2a] = {u00,u01,u02,u03}, T2[2a+1] = {u10..u13}.
template<int LBIT, int PB>
__device__ __forceinline__ void conv_mx(float (&st)[32], const float4* __restrict__ T2, int lane) {
    constexpr int Lm = 1 << LBIT, mb = 1 << PB;
    const int a = (lane >> LBIT) & 1;
    const float4 ua = T2[2 * a];
    const float4 ub = T2[2 * a + 1];
    #pragma unroll
    for (int r0 = 0; r0 < 32; ++r0) if (!(r0 & mb)) {
        const int r1 = r0 | mb;
        float p0 = shx(st[r0], Lm), p1 = shx(st[r1], Lm);
        float o0 = st[r0], o1 = st[r1];
        st[r0] = fmaf(ua.x, o0, fmaf(ua.y, o1, fmaf(ua.z, p0, ua.w * p1)));
        st[r1] = fmaf(ub.x, o0, fmaf(ub.y, o1, fmaf(ub.z, p0, ub.w * p1)));
    }
}

__global__ __launch_bounds__(256, 3)
void qcnn_kernel(const float* __restrict__ x, const float* __restrict__ adj,
                 const float* __restrict__ w_proj, const float* __restrict__ b_proj,
                 const float* __restrict__ qp,
                 const float* __restrict__ w1, const float* __restrict__ b1,
                 const float* __restrict__ w2, const float* __restrict__ b2,
                 const float* __restrict__ w3, const float* __restrict__ b3,
                 float* __restrict__ out) {
    __shared__ alignas(16) float UUs[14][16];      // full fused conv matrices (rr gates)
    __shared__ alignas(16) float UMX[8][2][8];     // mx gates: [gate][laneBit a][8 coefs]
    __shared__ float poolc[4], pools[4];           // FULL-angle cos/sin of pool RYs
    __shared__ alignas(16) float w1s[512];         // w1 natural [64][8]
    __shared__ float4 w2p4[32 * 17];               // w2 rows padded to 68 floats
    __shared__ float4 h1buf4[CPB * 17];
    __shared__ float zbuf[CPB][8];                 // im-warp reduce-scattered z
    __shared__ float b1s[64], b2s[32], w3s[32];
    __shared__ float b3s;

    const int tid = threadIdx.x;

    // ---- build fused conv matrices U = C2 * G2 * C1 * G1 ----
    if (tid < 14) {
        const int layer = tid / 7, pi = tid - 7 * layer;
        const int base = layer * 28 + pi * 4;
        float c0, s0, c1, s1, c2, s2, c3, s3;
        sincosf(0.5f * qp[base + 0], &s0, &c0);
        sincosf(0.5f * qp[base + 1], &s1, &c1);
        sincosf(0.5f * qp[base + 2], &s2, &c2);
        sincosf(0.5f * qp[base + 3], &s3, &c3);
        float R0[2][2] = {{c0, -s0}, {s0, c0}};
        float R1[2][2] = {{c1, -s1}, {s1, c1}};
        float R2m[2][2] = {{c2, -s2}, {s2, c2}};
        float R3[2][2] = {{c3, -s3}, {s3, c3}};
        float A[4][4], G2m[4][4], Bm[4][4], Cm[4][4];
        #pragma unroll
        for (int ap = 0; ap < 2; ++ap)
        #pragma unroll
        for (int bp = 0; bp < 2; ++bp)
        #pragma unroll
        for (int aq = 0; aq < 2; ++aq)
        #pragma unroll
        for (int bq = 0; bq < 2; ++bq) {
            A[2 * ap + bp][2 * aq + bq]   = R0[ap][aq] * R1[bp][bq];
            G2m[2 * ap + bp][2 * aq + bq] = R2m[ap][aq] * R3[bp][bq];
        }
        const int sig1[4] = {0, 1, 3, 2};
        const int sig2[4] = {0, 3, 2, 1};
        #pragma unroll
        for (int xr = 0; xr < 4; ++xr)
            #pragma unroll
            for (int m = 0; m < 4; ++m) Bm[xr][m] = A[sig1[xr]][m];
        #pragma unroll
        for (int xr = 0; xr < 4; ++xr)
            #pragma unroll
            for (int m = 0; m < 4; ++m) {
                float acc = 0.f;
                #pragma unroll
                for (int y = 0; y < 4; ++y) acc = fmaf(G2m[xr][y], Bm[y][m], acc);
                Cm[xr][m] = acc;
            }
        float Uf[16];
        #pragma unroll
        for (int xr = 0; xr < 4; ++xr)
            #pragma unroll
            for (int m = 0; m < 4; ++m) {
                Uf[xr * 4 + m] = Cm[sig2[xr]][m];
                UUs[tid][xr * 4 + m] = Cm[sig2[xr]][m];
            }
        // mx-gate coefficient tables. gates-in-layer 0,2,3,6 are mixed;
        // LQ1 (lane qubit first in the pair) for 0 and 6.
        int mxslot = -1; bool lq1 = false;
        if (pi == 0) { mxslot = 0; lq1 = true; }
        else if (pi == 2) { mxslot = 1; lq1 = false; }
        else if (pi == 3) { mxslot = 2; lq1 = false; }
        else if (pi == 6) { mxslot = 3; lq1 = true; }
        if (mxslot >= 0) {
            #pragma unroll
            for (int a = 0; a < 2; ++a) {
                int r0, r1, d0, d1;
                if (lq1) { r0 = 2 * a; r1 = 2 * a + 1; d0 = 2 * (a ^ 1); d1 = d0 + 1; }
                else     { r0 = a;     r1 = 2 + a;     d0 = a ^ 1;       d1 = 2 + (a ^ 1); }
                float* dst = &UMX[layer * 4 + mxslot][a][0];
                dst[0] = Uf[r0 * 4 + r0]; dst[1] = Uf[r0 * 4 + r1];
                dst[2] = Uf[r0 * 4 + d0]; dst[3] = Uf[r0 * 4 + d1];
                dst[4] = Uf[r1 * 4 + r0]; dst[5] = Uf[r1 * 4 + r1];
                dst[6] = Uf[r1 * 4 + d0]; dst[7] = Uf[r1 * 4 + d1];
            }
        }
    }
    if (tid >= 16 && tid < 20) {
        float s, c;
        sincosf(qp[56 + 2 * (tid - 16)], &s, &c);   // FULL angle (fused pooling)
        poolc[tid - 16] = c; pools[tid - 16] = s;
    }
    for (int i = tid; i < 512; i += 256) w1s[i] = w1[i];
    for (int i = tid; i < 2048; i += 256) {
        int row = i >> 6, j = i & 63;
        ((float*)w2p4)[row * 68 + j] = w2[i];
    }
    if (tid < 64) b1s[tid] = b1[tid];
    if (tid >= 64 && tid < 96) b2s[tid - 64] = b2[tid - 64];
    if (tid >= 96 && tid < 128) w3s[tid - 96] = w3[tid - 96];
    if (tid == 20) b3s = b3[0];
    __syncthreads();

    const int wid = tid >> 5;
    const int lane = tid & 31;
    const int comp = wid & 1;                 // 0 = re warp, 1 = im warp
    const int pairid = wid >> 1;              // 0..3
    const int ci = lane >> 3;                 // circuit-in-warp
    const int g = lane & 7;
    const int cb = pairid * 4 + ci;           // circuit-in-block 0..15
    const int cir = blockIdx.x * CPB + cb;
    const int b = cir / N_;
    const int n = cir - b * N_;

    // ---- angle projection: lane computes angle q = g of its circuit ----
    float av;
    {
        av = b_proj[g];
        const float* wrow = w_proj + g * (S_ * F_);
        const float* xb = x + (size_t)b * (S_ * N_ * F_) + n * F_;
        #pragma unroll
        for (int s = 0; s < S_; ++s) {
            float2 xv = *(const float2*)(xb + s * (N_ * F_));
            av = fmaf(wrow[2 * s], xv.x, av);
            av = fmaf(wrow[2 * s + 1], xv.y, av);
        }
        av = fminf(fmaxf(av, -PI_F), PI_F);
    }
    float sv, cv;
    __sincosf(0.5f * av, &sv, &cv);
    float ch[8], sh[8];
    #pragma unroll
    for (int q = 0; q < 8; ++q) {
        ch[q] = __shfl_sync(FULL, cv, (lane & 24) | q);
        sh[q] = __shfl_sync(FULL, sv, (lane & 24) | q);
    }

    // ---- graph CNOT mask (needed before construction) ----
    const int c = n & 7;
    const int pcq = (0x50612347u >> (4 * c)) & 0xF;    // posOf[c]
    int cond = (adj[c * N_ + g] > 0.f) && (g != c);
    const unsigned bal = __ballot_sync(FULL, cond);
    const unsigned mask8 = (bal >> (ci * 8)) & 0xFFu;
    constexpr int posOf[8] = {7, 4, 3, 2, 1, 6, 0, 5};
    int M = 0;
    #pragma unroll
    for (int t = 0; t < 8; ++t) M |= (int)((mask8 >> t) & 1u) << posOf[t];
    const int glm = (M >> 5) & 7;
    const int MR = M & 31;
    // bcmask bit r = control bit of flat index (g<<5)|r
    unsigned bcmask = (pcq == 0) ? 0xAAAAAAAAu : (pcq == 1) ? 0xCCCCCCCCu :
                      (pcq == 2) ? 0xF0F0F0F0u : (pcq == 3) ? 0xFF00FF00u : 0xFFFF0000u;
    if (pcq >= 5) bcmask = ((g >> (pcq - 5)) & 1) ? 0xFFFFFFFFu : 0u;

    // ---- build product state DIRECTLY PERMUTED by the graph CNOTs ----
    const int bq0 = (g >> 2) & 1, bq5 = (g >> 1) & 1, bq7 = g & 1;
    const int gp = g ^ glm;
    const int pp0 = (gp >> 2) & 1, pp5 = (gp >> 1) & 1, pp7 = gp & 1;

    const float magL0 = (bq0 ? sh[0] : ch[0]) * (bq5 ? sh[5] : ch[5]) * (bq7 ? sh[7] : ch[7]);
    const float magL1 = (pp0 ? sh[0] : ch[0]) * (pp5 ? sh[5] : ch[5]) * (pp7 ? sh[7] : ch[7]);
    const float ssA = bq0 ? sh[4] : -sh[4];
    const float ssB = pp0 ? sh[4] : -sh[4];
    const float ssx0 = comp ? ssA : -ssA;
    const float ssx1 = comp ? ssB : -ssB;

    float u23r[4], u23i[4];
    #pragma unroll
    for (int k = 0; k < 4; ++k) {
        const float s6 = (k & 2) ? sh[6] : -sh[6];
        const float s7 = (k & 1) ? sh[7] : -sh[7];
        u23r[k] = fmaf(ch[6], ch[7], -s6 * s7);
        u23i[k] = fmaf(ch[6], s7, s6 * ch[7]);
    }
    float B0[8], B1[8];
    #pragma unroll
    for (int t = 0; t < 8; ++t) {
        const float s5 = (t & 4) ? sh[5] : -sh[5];
        const float ur = fmaf(ch[5], u23r[t & 3], -s5 * u23i[t & 3]);
        const float ui = fmaf(ch[5], u23i[t & 3], s5 * u23r[t & 3]);
        const float P = comp ? ui : ur;
        const float Q = comp ? ur : ui;
        const float mg = ((t & 4) ? sh[1] : ch[1]) * ((t & 2) ? sh[2] : ch[2])
                       * ((t & 1) ? sh[3] : ch[3]);
        B0[t] = magL0 * mg * fmaf(ch[4], P, ssx0 * Q);
        B1[t] = magL1 * mg * fmaf(ch[4], P, ssx1 * Q);
    }
    const int Mt = (MR >> 2) & 7, Mlr = MR & 3;
    float Bp[8];
    {
        float ta[8], tb[8];
        #pragma unroll
        for (int t = 0; t < 8; ++t) ta[t] = (Mt & 1) ? B1[t ^ 1] : B1[t];
        #pragma unroll
        for (int t = 0; t < 8; ++t) tb[t] = (Mt & 2) ? ta[t ^ 2] : ta[t];
        #pragma unroll
        for (int t = 0; t < 8; ++t) Bp[t] = (Mt & 4) ? tb[t ^ 4] : tb[t];
    }
    float mA[4], mp[4];
    mA[0] = ch[4] * ch[6]; mA[1] = ch[4] * sh[6];
    mA[2] = sh[4] * ch[6]; mA[3] = sh[4] * sh[6];
    {
        float tm[4];
        #pragma unroll
        for (int l = 0; l < 4; ++l) tm[l] = (Mlr & 1) ? mA[l ^ 1] : mA[l];
        #pragma unroll
        for (int l = 0; l < 4; ++l) mp[l] = (Mlr & 2) ? tm[l ^ 2] : tm[l];
    }
    float st[32];
    #pragma unroll
    for (int t = 0; t < 8; ++t)
        #pragma unroll
        for (int l = 0; l < 4; ++l) {
            const int r = 4 * t + l;
            const bool bc = (bcmask >> r) & 1u;
            st[r] = (bc ? Bp[t] : B0[t]) * (bc ? mp[l] : mA[l]);
        }

    // ---- 2 conv layers ----
    #pragma unroll
    for (int l = 0; l < 2; ++l) {
        const float4* Ub = (const float4*)UUs[l * 7];
        conv_mx<2, 4>(st, (const float4*)UMX[l * 4 + 0], lane);   // (q0,q1)
        conv_rr<3, 2>(st, Ub + 1 * 4);                            // (q2,q3)
        conv_mx<1, 1>(st, (const float4*)UMX[l * 4 + 1], lane);   // (q4,q5)
        conv_mx<0, 0>(st, (const float4*)UMX[l * 4 + 2], lane);   // (q6,q7)
        conv_rr<4, 3>(st, Ub + 4 * 4);                            // (q1,q2)
        conv_rr<2, 1>(st, Ub + 5 * 4);                            // (q3,q4)
        conv_mx<1, 0>(st, (const float4*)UMX[l * 4 + 3], lane);   // (q5,q6)
    }

    // ---- measurement with POOLING FUSED IN ----
    // crosses first (st must be live for shuffles/pairs)
    float x2 = 0.f, x4 = 0.f, x6 = 0.f, c0x = 0.f;
    #pragma unroll
    for (int r = 0; r < 32; ++r) {
        if (!(r & 8)) x2 = fmaf(st[r], st[r | 8], x2);   // q2 pairs
        if (!(r & 2)) x4 = fmaf(st[r], st[r | 2], x4);   // q4 pairs
        if (!(r & 1)) x6 = fmaf(st[r], st[r | 1], x6);   // q6 pairs
        c0x = fmaf(st[r], shx(st[r], 4), c0x);           // q0 cross (lane bit 2)
    }
    // Walsh tree for tot, z1..z4, z6 (r bits: 4=q1, 3=q2, 2=q3, 1=q4, 0=q6)
    float s0[16], e6 = 0.f;
    #pragma unroll
    for (int k = 0; k < 16; ++k) {
        float pe = st[2 * k] * st[2 * k];
        float po = st[2 * k + 1] * st[2 * k + 1];
        s0[k] = pe + po;
        e6 += pe;
    }
    float s1[8], e4 = 0.f;
    #pragma unroll
    for (int m = 0; m < 8; ++m) { s1[m] = s0[2 * m] + s0[2 * m + 1]; e4 += s0[2 * m]; }
    float s2[4], e3 = 0.f;
    #pragma unroll
    for (int n2 = 0; n2 < 4; ++n2) { s2[n2] = s1[2 * n2] + s1[2 * n2 + 1]; e3 += s1[2 * n2]; }
    const float e2 = s2[0] + s2[2];
    const float s3a = s2[0] + s2[1], s3b = s2[2] + s2[3];
    const float tot = s3a + s3b;
    const float z1 = s3a - s3b;
    const float z2r = fmaf(2.f, e2, -tot);
    const float z3r = fmaf(2.f, e3, -tot);
    const float z4r = fmaf(2.f, e4, -tot);
    const float z6r = fmaf(2.f, e6, -tot);

    float z[8];
    z[0] = fmaf(poolc[0], (bq0 ? -tot : tot), -pools[0] * c0x);
    z[2] = fmaf(poolc[1], z2r, -2.f * pools[1] * x2);
    z[4] = fmaf(poolc[2], z4r, -2.f * pools[2] * x4);
    z[6] = fmaf(poolc[3], z6r, -2.f * pools[3] * x6);
    z[1] = z1; z[3] = z3r;
    z[5] = bq5 ? -tot : tot;
    z[7] = bq7 ? -tot : tot;

    // ---- reduce-scatter over the 8-lane group: lane g ends with Z[g] ----
    float zg;
    {
        const int b2l = bq0, b1l = bq5, b0l = bq7;   // lane bits 2,1,0
        float v[4];
        #pragma unroll
        for (int j = 0; j < 4; ++j) {
            float keep = b2l ? z[j + 4] : z[j];
            float send = b2l ? z[j] : z[j + 4];
            v[j] = keep + shx(send, 4);
        }
        float u0 = (b1l ? v[2] : v[0]) + shx(b1l ? v[0] : v[2], 2);
        float u1 = (b1l ? v[3] : v[1]) + shx(b1l ? v[1] : v[3], 2);
        zg = (b0l ? u1 : u0) + shx(b0l ? u0 : u1, 1);
    }

    // im warp publishes its Z[g]; re warp combines and runs the MLP
    if (comp) zbuf[cb][g] = zg;
    __syncthreads();

    if (!comp) {
        zg += zbuf[cb][g];
        float z8[8];
        #pragma unroll
        for (int w = 0; w < 8; ++w)
            z8[w] = __shfl_sync(FULL, zg, (lane & 24) | w);

        // ---- MLP head: 8 -> 64 -> 32 -> 1 ----
        float h1v[8];
        const float* w1row = w1s + g * 64;
        #pragma unroll
        for (int i = 0; i < 8; ++i) {
            float4 wa = *(const float4*)(w1row + i * 8);
            float4 wb = *(const float4*)(w1row + i * 8 + 4);
            float acc = b1s[8 * g + i];
            acc = fmaf(wa.x, z8[0], acc); acc = fmaf(wa.y, z8[1], acc);
            acc = fmaf(wa.z, z8[2], acc); acc = fmaf(wa.w, z8[3], acc);
            acc = fmaf(wb.x, z8[4], acc); acc = fmaf(wb.y, z8[5], acc);
            acc = fmaf(wb.z, z8[6], acc); acc = fmaf(wb.w, z8[7], acc);
            h1v[i] = fmaxf(acc, 0.f);
        }
        {
            float4* dst = (float4*)((float*)h1buf4 + cb * 68 + 8 * g);
            dst[0] = make_float4(h1v[0], h1v[1], h1v[2], h1v[3]);
            dst[1] = make_float4(h1v[4], h1v[5], h1v[6], h1v[7]);
        }
        __syncwarp();

        // h2: this lane computes rows g, g+8, g+16, g+24
        float acc2[4];
        #pragma unroll
        for (int i = 0; i < 4; ++i) acc2[i] = b2s[g + 8 * i];
        const float4* h1p = h1buf4 + cb * 17;
        #pragma unroll
        for (int j4 = 0; j4 < 16; ++j4) {
            float4 h = h1p[j4];
            #pragma unroll
            for (int i = 0; i < 4; ++i) {
                float4 w = w2p4[(g + 8 * i) * 17 + j4];
                acc2[i] = fmaf(w.x, h.x, fmaf(w.y, h.y, fmaf(w.z, h.z, fmaf(w.w, h.w, acc2[i]))));
            }
        }
        float o = 0.f;
        #pragma unroll
        for (int i = 0; i < 4; ++i)
            o = fmaf(w3s[g + 8 * i], fmaxf(acc2[i], 0.f), o);
        o += shx(o, 1); o += shx(o, 2); o += shx(o, 4);
        if (g == 0) out[cir] = o + b3s;
    }
}

extern "C" void kernel_launch(void* const* d_in, const int* in_sizes, int n_in,
                              void* d_out, int out_size) {
    const float* x      = (const float*)d_in[0];
    const float* adj    = (const float*)d_in[1];
    const float* w_proj = (const float*)d_in[2];
    const float* b_proj = (const float*)d_in[3];
    const float* qp     = (const float*)d_in[4];
    const float* w1     = (const float*)d_in[5];
    const float* b1     = (const float*)d_in[6];
    const float* w2     = (const float*)d_in[7];
    const float* b2     = (const float*)d_in[8];
    const float* w3     = (const float*)d_in[9];
    const float* b3     = (const float*)d_in[10];
    float* out = (float*)d_out;

    const int blocks = NCIRC / CPB;   // 828
    qcnn_kernel<<<blocks, 256>>>(x, adj, w_proj, b_proj, qp,
                                 w1, b1, w2, b2, w3, b3, out);
}